// round 4
// baseline (speedup 1.0000x reference)
#include <cuda_runtime.h>
#include <math.h>
#include <stdint.h>

#define NB 4
#define SEQ 128
#define DL 128
#define DM 16
#define SO 120
#define ROWS (NB*SEQ)        // 512

typedef unsigned long long u64;

// packed fp32x2 FMA (sm_100+): d = a*b + c on both 32-bit halves
#define FMA2(d,a,b,c) asm("fma.rn.f32x2 %0, %1, %2, %3;" : "=l"(d) : "l"(a), "l"(b), "l"(c))
#define DUP2(d,s)     asm("mov.b64 %0, {%1, %1};" : "=l"(d) : "r"(__float_as_uint(s)))
#define UNPK2(lo,hi,p) asm("mov.b64 {%0, %1}, %2;" : "=r"(lo), "=r"(hi) : "l"(p))
#define LDS_2x64(p0,p1,addr) asm volatile("ld.shared.v2.b64 {%0, %1}, [%2];" : "=l"(p0), "=l"(p1) : "r"(addr))

// ---------------- scratch (device globals; no allocations allowed) ----------
__device__ float g_Q[ROWS*DL];
__device__ float g_K[ROWS*DL];
__device__ float g_U[ROWS*256];
__device__ float g_attn[NB*SEQ*SEQ];
__device__ float g_lie[(size_t)NB*SEQ*SEQ*SO];   // 31.5 MB
__device__ float g_settled[ROWS*DM];

__constant__ int c_tri_r[120] = {
 0,0,0,0,0,0,0,0,0,0,0,0,0,0,0,
 1,1,1,1,1,1,1,1,1,1,1,1,1,1,
 2,2,2,2,2,2,2,2,2,2,2,2,2,
 3,3,3,3,3,3,3,3,3,3,3,3,
 4,4,4,4,4,4,4,4,4,4,4,
 5,5,5,5,5,5,5,5,5,5,
 6,6,6,6,6,6,6,6,6,
 7,7,7,7,7,7,7,7,
 8,8,8,8,8,8,8,
 9,9,9,9,9,9,
 10,10,10,10,10,
 11,11,11,11,
 12,12,12,
 13,13,
 14};
__constant__ int c_tri_c[120] = {
 1,2,3,4,5,6,7,8,9,10,11,12,13,14,15,
 2,3,4,5,6,7,8,9,10,11,12,13,14,15,
 3,4,5,6,7,8,9,10,11,12,13,14,15,
 4,5,6,7,8,9,10,11,12,13,14,15,
 5,6,7,8,9,10,11,12,13,14,15,
 6,7,8,9,10,11,12,13,14,15,
 7,8,9,10,11,12,13,14,15,
 8,9,10,11,12,13,14,15,
 9,10,11,12,13,14,15,
 10,11,12,13,14,15,
 11,12,13,14,15,
 12,13,14,15,
 13,14,15,
 14,15,
 15};

__device__ __forceinline__ float ftanh(float x) {
    float y;
    asm("tanh.approx.f32 %0, %1;" : "=f"(y) : "f"(x));
    return y;
}

// ---------------- kernel A: tiled GEMM  C[512 x 512] = X @ [Wq;Wk;W1]^T ----
__global__ void __launch_bounds__(256)
prep_kernel(const float* __restrict__ xl,
            const float* __restrict__ Wq, const float* __restrict__ bq,
            const float* __restrict__ Wk, const float* __restrict__ bk,
            const float* __restrict__ W1)
{
    __shared__ __align__(16) float Xs[64*64];
    __shared__ __align__(16) float Wt[64*68];

    int bx = blockIdx.x, by = blockIdx.y;
    int t  = threadIdx.x;
    int tx = t & 15, ty = t >> 4;

    const float* src;
    if      (by < 2) src = Wq + (by    )*64*DL;
    else if (by < 4) src = Wk + (by - 2)*64*DL;
    else             src = W1 + (by - 4)*64*DL;

    float acc[4][4];
    #pragma unroll
    for (int i = 0; i < 4; i++)
        #pragma unroll
        for (int j = 0; j < 4; j++) acc[i][j] = 0.f;

    for (int k0 = 0; k0 < DL; k0 += 64) {
        __syncthreads();
        #pragma unroll
        for (int s = 0; s < 16; s++) {
            int idx = t + 256*s;
            int r = idx >> 6, k = idx & 63;
            Xs[r*64 + k] = xl[(bx*64 + r)*DL + k0 + k];
            Wt[k*68 + r] = src[r*DL + k0 + k];
        }
        __syncthreads();

        #pragma unroll 8
        for (int k = 0; k < 64; k++) {
            float4 bv = *(const float4*)&Wt[k*68 + tx*4];
            #pragma unroll
            for (int i = 0; i < 4; i++) {
                float a = Xs[(ty*4 + i)*64 + k];
                acc[i][0] = fmaf(a, bv.x, acc[i][0]);
                acc[i][1] = fmaf(a, bv.y, acc[i][1]);
                acc[i][2] = fmaf(a, bv.z, acc[i][2]);
                acc[i][3] = fmaf(a, bv.w, acc[i][3]);
            }
        }
    }

    #pragma unroll
    for (int i = 0; i < 4; i++) {
        int rowg = bx*64 + ty*4 + i;
        int c0   = tx*4;
        if (by < 2) {
            int col = by*64 + c0;
            *(float4*)&g_Q[rowg*DL + col] =
                make_float4(acc[i][0]+bq[col], acc[i][1]+bq[col+1],
                            acc[i][2]+bq[col+2], acc[i][3]+bq[col+3]);
        } else if (by < 4) {
            int col = (by-2)*64 + c0;
            *(float4*)&g_K[rowg*DL + col] =
                make_float4(acc[i][0]+bk[col], acc[i][1]+bk[col+1],
                            acc[i][2]+bk[col+2], acc[i][3]+bk[col+3]);
        } else {
            int col = (by-4)*64 + c0;
            *(float4*)&g_U[rowg*256 + col] =
                make_float4(acc[i][0], acc[i][1], acc[i][2], acc[i][3]);
        }
    }
}

// ---------------- kernel B: attention softmax (+ zero g_settled) -----------
#define AT_QS 0
#define AT_KT (AT_QS + 32*128)
#define AT_S  (AT_KT + 128*132)
#define AT_FLOATS (AT_S + 32*132)
#define AT_BYTES  (AT_FLOATS*4)

__global__ void __launch_bounds__(256)
attn_kernel()
{
    extern __shared__ float sm[];
    float* Qs = sm + AT_QS;
    float* Kt = sm + AT_KT;
    float* S  = sm + AT_S;

    int b  = blockIdx.x >> 2;
    int jt = (blockIdx.x & 3) * 32;
    int t  = threadIdx.x;
    int tx = t & 15, ty = t >> 4;

    for (int z = t; z < 512; z += 256) g_settled[blockIdx.x*512 + z] = 0.f;

    for (int idx = t; idx < 32*128; idx += 256) {
        int j = idx >> 7, k = idx & 127;
        Qs[j*128 + k] = g_Q[(b*SEQ + jt + j)*DL + k];
    }
    for (int idx = t; idx < 128*128; idx += 256) {
        int i = idx >> 7, k = idx & 127;
        Kt[k*132 + i] = g_K[(b*SEQ + i)*DL + k];
    }
    __syncthreads();

    float acc[2][8];
    #pragma unroll
    for (int i = 0; i < 2; i++)
        #pragma unroll
        for (int j = 0; j < 8; j++) acc[i][j] = 0.f;

    int j0 = ty*2, i0 = tx*8;
    #pragma unroll 4
    for (int k = 0; k < 128; k++) {
        float q0 = Qs[(j0  )*128 + k];
        float q1 = Qs[(j0+1)*128 + k];
        float4 k0v = *(const float4*)&Kt[k*132 + i0];
        float4 k1v = *(const float4*)&Kt[k*132 + i0 + 4];
        acc[0][0]=fmaf(q0,k0v.x,acc[0][0]); acc[0][1]=fmaf(q0,k0v.y,acc[0][1]);
        acc[0][2]=fmaf(q0,k0v.z,acc[0][2]); acc[0][3]=fmaf(q0,k0v.w,acc[0][3]);
        acc[0][4]=fmaf(q0,k1v.x,acc[0][4]); acc[0][5]=fmaf(q0,k1v.y,acc[0][5]);
        acc[0][6]=fmaf(q0,k1v.z,acc[0][6]); acc[0][7]=fmaf(q0,k1v.w,acc[0][7]);
        acc[1][0]=fmaf(q1,k0v.x,acc[1][0]); acc[1][1]=fmaf(q1,k0v.y,acc[1][1]);
        acc[1][2]=fmaf(q1,k0v.z,acc[1][2]); acc[1][3]=fmaf(q1,k0v.w,acc[1][3]);
        acc[1][4]=fmaf(q1,k1v.x,acc[1][4]); acc[1][5]=fmaf(q1,k1v.y,acc[1][5]);
        acc[1][6]=fmaf(q1,k1v.z,acc[1][6]); acc[1][7]=fmaf(q1,k1v.w,acc[1][7]);
    }
    const float sc = 0.08838834764831845f;
    #pragma unroll
    for (int i = 0; i < 2; i++) {
        *(float4*)&S[(j0+i)*132 + i0] =
            make_float4(acc[i][0]*sc, acc[i][1]*sc, acc[i][2]*sc, acc[i][3]*sc);
        *(float4*)&S[(j0+i)*132 + i0 + 4] =
            make_float4(acc[i][4]*sc, acc[i][5]*sc, acc[i][6]*sc, acc[i][7]*sc);
    }
    __syncthreads();

    int w = t >> 5, lane = t & 31;
    for (int q = 0; q < 4; q++) {
        int r = w*4 + q;
        float v0 = S[r*132 + lane      ];
        float v1 = S[r*132 + lane + 32 ];
        float v2 = S[r*132 + lane + 64 ];
        float v3 = S[r*132 + lane + 96 ];
        float mx = fmaxf(fmaxf(v0,v1), fmaxf(v2,v3));
        #pragma unroll
        for (int off = 16; off; off >>= 1)
            mx = fmaxf(mx, __shfl_xor_sync(0xffffffffu, mx, off));
        float e0 = expf(v0-mx), e1 = expf(v1-mx), e2 = expf(v2-mx), e3 = expf(v3-mx);
        float sum = e0+e1+e2+e3;
        #pragma unroll
        for (int off = 16; off; off >>= 1)
            sum += __shfl_xor_sync(0xffffffffu, sum, off);
        float inv = 1.f/sum;
        float* dst = g_attn + (b*SEQ + jt + r)*SEQ;
        dst[lane     ] = e0*inv;
        dst[lane + 32] = e1*inv;
        dst[lane + 64] = e2*inv;
        dst[lane + 96] = e3*inv;
    }
}

// ---------------- kernel C: pairwise MLP GEMM -> g_lie  (FFMA2) ------------
__global__ void __launch_bounds__(256, 2)
pair_kernel(const float* __restrict__ b1, const float* __restrict__ W2,
            const float* __restrict__ b2)
{
    __shared__ __align__(16) float Ujb[256];
    __shared__ __align__(16) float As[32*132];   // [kk][i]
    __shared__ __align__(16) float Bs[32*132];   // [kk][c]

    int row = blockIdx.x;          // b*128 + j
    int b   = row >> 7;
    int t   = threadIdx.x;

    Ujb[t] = g_U[row*256 + t] + b1[t];

    int i0 = (t & 15) * 8;
    int c0 = (t >> 4) * 8;

    unsigned asBase = (unsigned)__cvta_generic_to_shared(As) + i0*4;
    unsigned bsBase = (unsigned)__cvta_generic_to_shared(Bs) + c0*4;

    u64 acc2[8][4];
    #pragma unroll
    for (int i = 0; i < 8; i++)
        #pragma unroll
        for (int j = 0; j < 4; j++) acc2[i][j] = 0ull;

    for (int k0 = 0; k0 < 256; k0 += 32) {
        __syncthreads();
        #pragma unroll
        for (int s = 0; s < 16; s++) {
            int idx = t + 256*s;          // 4096
            int i = idx >> 5, kk = idx & 31;
            float u = g_U[(b*SEQ + i)*256 + k0 + kk];
            As[kk*132 + i] = ftanh(Ujb[k0 + kk] - u);
        }
        #pragma unroll
        for (int s = 0; s < 15; s++) {
            int idx = t + 256*s;          // 3840
            int c = idx >> 5, kk = idx & 31;
            Bs[kk*132 + c] = W2[c*256 + k0 + kk];
        }
        { int c = 120 + (t >> 5), kk = t & 31; Bs[kk*132 + c] = 0.f; }
        __syncthreads();

        #pragma unroll
        for (int kk = 0; kk < 32; kk++) {
            unsigned aAddr = asBase + kk*132*4;
            unsigned bAddr = bsBase + kk*132*4;
            float4 aA = *(const float4*)&As[kk*132 + i0];
            float4 aB = *(const float4*)&As[kk*132 + i0 + 4];
            u64 b01, b23, b45, b67;
            LDS_2x64(b01, b23, bAddr);
            LDS_2x64(b45, b67, bAddr + 16);
            (void)aAddr;
            float av[8] = {aA.x,aA.y,aA.z,aA.w,aB.x,aB.y,aB.z,aB.w};
            #pragma unroll
            for (int i = 0; i < 8; i++) {
                u64 ad; DUP2(ad, av[i]);
                FMA2(acc2[i][0], ad, b01, acc2[i][0]);
                FMA2(acc2[i][1], ad, b23, acc2[i][1]);
                FMA2(acc2[i][2], ad, b45, acc2[i][2]);
                FMA2(acc2[i][3], ad, b67, acc2[i][3]);
            }
        }
    }

    if (c0 < SO) {
        float4 bb0 = *(const float4*)&b2[c0];
        float4 bb1 = *(const float4*)&b2[c0 + 4];
        float bb[8] = {bb0.x,bb0.y,bb0.z,bb0.w,bb1.x,bb1.y,bb1.z,bb1.w};
        #pragma unroll
        for (int ii = 0; ii < 8; ii++) {
            float v[8];
            #pragma unroll
            for (int jp = 0; jp < 4; jp++) {
                unsigned lo, hi;
                UNPK2(lo, hi, acc2[ii][jp]);
                v[2*jp]   = __uint_as_float(lo) + bb[2*jp];
                v[2*jp+1] = __uint_as_float(hi) + bb[2*jp+1];
            }
            size_t p = (size_t)row*SEQ + (i0 + ii);
            float* dst = g_lie + p*SO + c0;
            *(float4*)dst     = make_float4(v[0],v[1],v[2],v[3]);
            *(float4*)(dst+4) = make_float4(v[4],v[5],v[6],v[7]);
        }
    }
}

// ---------------- warp 16x16 matmul (FFMA2, A preloaded) -------------------
__device__ __forceinline__ void wmm2(const float* __restrict__ A,
                                     unsigned Bsh,       // shared addr of B base
                                     float reg[2][4], int r0, int c0)
{
    float a0[16], a1[16];
    #pragma unroll
    for (int q = 0; q < 4; q++) {
        float4 v0 = *(const float4*)&A[(r0  )*20 + 4*q];
        float4 v1 = *(const float4*)&A[(r0+1)*20 + 4*q];
        a0[4*q]=v0.x; a0[4*q+1]=v0.y; a0[4*q+2]=v0.z; a0[4*q+3]=v0.w;
        a1[4*q]=v1.x; a1[4*q+1]=v1.y; a1[4*q+2]=v1.z; a1[4*q+3]=v1.w;
    }
    u64 c00=0ull, c01=0ull, c10=0ull, c11=0ull;
    #pragma unroll
    for (int k = 0; k < 16; k++) {
        u64 b0, b1;
        LDS_2x64(b0, b1, Bsh + (k*20 + c0)*4);
        u64 ad0, ad1;
        DUP2(ad0, a0[k]); DUP2(ad1, a1[k]);
        FMA2(c00, ad0, b0, c00); FMA2(c01, ad0, b1, c01);
        FMA2(c10, ad1, b0, c10); FMA2(c11, ad1, b1, c11);
    }
    unsigned lo, hi;
    UNPK2(lo, hi, c00); reg[0][0]=__uint_as_float(lo); reg[0][1]=__uint_as_float(hi);
    UNPK2(lo, hi, c01); reg[0][2]=__uint_as_float(lo); reg[0][3]=__uint_as_float(hi);
    UNPK2(lo, hi, c10); reg[1][0]=__uint_as_float(lo); reg[1][1]=__uint_as_float(hi);
    UNPK2(lo, hi, c11); reg[1][2]=__uint_as_float(lo); reg[1][3]=__uint_as_float(hi);
}

__device__ __forceinline__ void wstore20(float* __restrict__ C, const float reg[2][4],
                                         int r0, int c0)
{
    *(float4*)&C[(r0  )*20 + c0] = make_float4(reg[0][0],reg[0][1],reg[0][2],reg[0][3]);
    *(float4*)&C[(r0+1)*20 + c0] = make_float4(reg[1][0],reg[1][1],reg[1][2],reg[1][3]);
}

// ---------------- kernel D: expm + aggregate -------------------------------
__global__ void __launch_bounds__(128, 6)
expm_kernel(const float* __restrict__ xm_g, float* __restrict__ Tout)
{
    __shared__ __align__(16) float mm[4*4*320];
    int t = threadIdx.x, lane = t & 31, w = t >> 5;
    float* Abuf  = mm + w*1280;
    float* A2buf = Abuf + 320;
    float* A3buf = Abuf + 640;
    float* Tbuf  = Abuf + 960;
    unsigned AbufSh  = (unsigned)__cvta_generic_to_shared(Abuf);
    unsigned A3bufSh = AbufSh + 640*4;
    unsigned TbufSh  = AbufSh + 960*4;

    int r0m = (lane >> 2) * 2;
    int c0m = (lane & 3)  * 4;

    const float c3=1.f/6.f, c4=1.f/24.f, c5=1.f/120.f;
    const float c6=1.f/720.f, c7=1.f/5040.f, c8=1.f/40320.f, c9=1.f/362880.f;

    int p0 = blockIdx.x*64 + w*16;

    for (int m = 0; m < 16; m++) {
        int p   = p0 + m;
        int row = p >> 7;
        int i   = p & 127;
        int b   = row >> 7;

        // scatter lie -> skew A
        const float* lrow = g_lie + (size_t)p*SO;
        if (lane < 16) Abuf[lane*20 + lane] = 0.f;
        #pragma unroll
        for (int q = 0; q < 4; q++) {
            int l = lane + 32*q;
            if (l < SO) {
                float v = lrow[l];
                int rI = c_tri_r[l], cI = c_tri_c[l];
                Abuf[rI*20 + cI] =  v;
                Abuf[cI*20 + rI] = -v;
            }
        }
        __syncwarp();

        // inf-norm -> scaling exponent
        int myr = lane & 15;
        float4 n0 = *(const float4*)&Abuf[myr*20     ];
        float4 n1 = *(const float4*)&Abuf[myr*20 +  4];
        float4 n2 = *(const float4*)&Abuf[myr*20 +  8];
        float4 n3 = *(const float4*)&Abuf[myr*20 + 12];
        float rs = fabsf(n0.x)+fabsf(n0.y)+fabsf(n0.z)+fabsf(n0.w)
                 + fabsf(n1.x)+fabsf(n1.y)+fabsf(n1.z)+fabsf(n1.w)
                 + fabsf(n2.x)+fabsf(n2.y)+fabsf(n2.z)+fabsf(n2.w)
                 + fabsf(n3.x)+fabsf(n3.y)+fabsf(n3.z)+fabsf(n3.w);
        #pragma unroll
        for (int off = 8; off; off >>= 1)
            rs = fmaxf(rs, __shfl_xor_sync(0xffffffffu, rs, off));
        int sct = 0;
        if (rs > 1.f) { sct = (int)ceilf(log2f(rs)); if (sct > 12) sct = 12; }
        float scale = __uint_as_float((uint32_t)(127 - sct) << 23);
        #pragma unroll
        for (int q = 0; q < 8; q++) {
            int e = lane + 32*q;
            int rI = e >> 4, cI = e & 15;
            Abuf[rI*20 + cI] *= scale;
        }
        __syncwarp();

        float reg[2][4];
        // A2 = A*A
        wmm2(Abuf, AbufSh, reg, r0m, c0m);
        wstore20(A2buf, reg, r0m, c0m);  __syncwarp();
        // A3 = A2*A
        wmm2(A2buf, AbufSh, reg, r0m, c0m);
        wstore20(A3buf, reg, r0m, c0m);  __syncwarp();

        // B2 = c6 I + c7 A + c8 A2 + c9 A3  -> Tbuf (tiles read from smem)
        {
            float4 a0v  = *(const float4*)&Abuf [(r0m  )*20 + c0m];
            float4 a1v  = *(const float4*)&Abuf [(r0m+1)*20 + c0m];
            float4 p0v  = *(const float4*)&A2buf[(r0m  )*20 + c0m];
            float4 p1v  = *(const float4*)&A2buf[(r0m+1)*20 + c0m];
            float4 q0v  = *(const float4*)&A3buf[(r0m  )*20 + c0m];
            float4 q1v  = *(const float4*)&A3buf[(r0m+1)*20 + c0m];
            float tA [2][4] = {{a0v.x,a0v.y,a0v.z,a0v.w},{a1v.x,a1v.y,a1v.z,a1v.w}};
            float tA2[2][4] = {{p0v.x,p0v.y,p0v.z,p0v.w},{p1v.x,p1v.y,p1v.z,p1v.w}};
            float tA3[2][4] = {{q0v.x,q0v.y,q0v.z,q0v.w},{q1v.x,q1v.y,q1v.z,q1v.w}};
            #pragma unroll
            for (int ii = 0; ii < 2; ii++)
                #pragma unroll
                for (int jj = 0; jj < 4; jj++) {
                    float v = fmaf(c7, tA[ii][jj], fmaf(c8, tA2[ii][jj], c9 * tA3[ii][jj]));
                    if (r0m + ii == c0m + jj) v += c6;
                    reg[ii][jj] = v;
                }
            wstore20(Tbuf, reg, r0m, c0m);  __syncwarp();
        }

        // reg = A3*B2 + B1 -> Tbuf
        wmm2(A3buf, TbufSh, reg, r0m, c0m);  __syncwarp();
        {
            float4 a0v  = *(const float4*)&Abuf [(r0m  )*20 + c0m];
            float4 a1v  = *(const float4*)&Abuf [(r0m+1)*20 + c0m];
            float4 p0v  = *(const float4*)&A2buf[(r0m  )*20 + c0m];
            float4 p1v  = *(const float4*)&A2buf[(r0m+1)*20 + c0m];
            float tA [2][4] = {{a0v.x,a0v.y,a0v.z,a0v.w},{a1v.x,a1v.y,a1v.z,a1v.w}};
            float tA2[2][4] = {{p0v.x,p0v.y,p0v.z,p0v.w},{p1v.x,p1v.y,p1v.z,p1v.w}};
            #pragma unroll
            for (int ii = 0; ii < 2; ii++)
                #pragma unroll
                for (int jj = 0; jj < 4; jj++) {
                    reg[ii][jj] += fmaf(c4, tA[ii][jj], c5 * tA2[ii][jj]);
                    if (r0m + ii == c0m + jj) reg[ii][jj] += c3;
                }
            wstore20(Tbuf, reg, r0m, c0m);  __syncwarp();
        }

        // reg = A3*(B1 + A3*B2) + B0
        wmm2(A3buf, TbufSh, reg, r0m, c0m);
        {
            float4 a0v  = *(const float4*)&Abuf [(r0m  )*20 + c0m];
            float4 a1v  = *(const float4*)&Abuf [(r0m+1)*20 + c0m];
            float4 p0v  = *(const float4*)&A2buf[(r0m  )*20 + c0m];
            float4 p1v  = *(const float4*)&A2buf[(r0m+1)*20 + c0m];
            float tA [2][4] = {{a0v.x,a0v.y,a0v.z,a0v.w},{a1v.x,a1v.y,a1v.z,a1v.w}};
            float tA2[2][4] = {{p0v.x,p0v.y,p0v.z,p0v.w},{p1v.x,p1v.y,p1v.z,p1v.w}};
            #pragma unroll
            for (int ii = 0; ii < 2; ii++)
                #pragma unroll
                for (int jj = 0; jj < 4; jj++) {
                    reg[ii][jj] += fmaf(0.5f, tA2[ii][jj], tA[ii][jj]);
                    if (r0m + ii == c0m + jj) reg[ii][jj] += 1.f;
                }
        }

        // squarings
        for (int q = 0; q < sct; q++) {
            __syncwarp();
            wstore20(Tbuf, reg, r0m, c0m);
            __syncwarp();
            wmm2(Tbuf, TbufSh, reg, r0m, c0m);
        }

        // write T_all
        float* dst = Tout + (size_t)p*256;
        *(float4*)(dst + (r0m  )*16 + c0m) = make_float4(reg[0][0],reg[0][1],reg[0][2],reg[0][3]);
        *(float4*)(dst + (r0m+1)*16 + c0m) = make_float4(reg[1][0],reg[1][1],reg[1][2],reg[1][3]);

        // transported & settled
        float4 xv = *(const float4*)&xm_g[((size_t)b*SEQ + i)*DM + c0m];
        float p0v = reg[0][0]*xv.x + reg[0][1]*xv.y + reg[0][2]*xv.z + reg[0][3]*xv.w;
        float p1v = reg[1][0]*xv.x + reg[1][1]*xv.y + reg[1][2]*xv.z + reg[1][3]*xv.w;
        p0v += __shfl_xor_sync(0xffffffffu, p0v, 1);
        p0v += __shfl_xor_sync(0xffffffffu, p0v, 2);
        p1v += __shfl_xor_sync(0xffffffffu, p1v, 1);
        p1v += __shfl_xor_sync(0xffffffffu, p1v, 2);
        if ((lane & 3) == 0) {
            float wgt = g_attn[row*SEQ + i];
            atomicAdd(&g_settled[row*DM + r0m    ], wgt * p0v);
            atomicAdd(&g_settled[row*DM + r0m + 1], wgt * p1v);
        }
        __syncwarp();
    }
}

// ---------------- kernel E: out projection ---------------------------------
__global__ void __launch_bounds__(256)
out_kernel(const float* __restrict__ Wo, const float* __restrict__ bo,
           float* __restrict__ out)
{
    int gid = blockIdx.x*256 + threadIdx.x;    // 8192
    int row = gid >> 4, d = gid & 15;
    float acc = bo[d];
    #pragma unroll
    for (int e = 0; e < DM; e++)
        acc = fmaf(Wo[d*DM + e], g_settled[row*DM + e], acc);
    out[gid] = acc;
}

// ---------------- launch ----------------------------------------------------
extern "C" void kernel_launch(void* const* d_in, const int* in_sizes, int n_in,
                              void* d_out, int out_size)
{
    const float* xl  = (const float*)d_in[0];
    const float* xmm = (const float*)d_in[1];
    const float* Wq  = (const float*)d_in[2];
    const float* bq  = (const float*)d_in[3];
    const float* Wk  = (const float*)d_in[4];
    const float* bk  = (const float*)d_in[5];
    const float* W1  = (const float*)d_in[6];
    const float* b1  = (const float*)d_in[7];
    const float* W2  = (const float*)d_in[8];
    const float* b2  = (const float*)d_in[9];
    const float* Wo  = (const float*)d_in[10];
    const float* bo  = (const float*)d_in[11];

    float* out  = (float*)d_out;
    float* Tout = out + NB*SEQ*DM;      // T_all follows out

    static bool attr_set = false;
    if (!attr_set) {
        cudaFuncSetAttribute(attn_kernel, cudaFuncAttributeMaxDynamicSharedMemorySize, AT_BYTES);
        attr_set = true;
    }

    prep_kernel<<<dim3(8,8), 256>>>(xl, Wq, bq, Wk, bk, W1);
    attn_kernel<<<16, 256, AT_BYTES>>>();
    pair_kernel<<<ROWS, 256>>>(b1, W2, b2);
    expm_kernel<<<1024, 128>>>(xmm, Tout);
    out_kernel<<<32, 256>>>(Wo, bo, out);
}